// round 7
// baseline (speedup 1.0000x reference)
#include <cuda_runtime.h>
#include <cuda_bf16.h>
#include <math.h>
#include <stdint.h>

#define NDEG 9
struct Coeffs { float a[NDEG + 1]; float s1, s0; };

// smem: bf16 B matrices (T, T3 as hi/lo) + fp32 T2 scratch.
#define BSTRIDE 72
#define BMATB   (64 * BSTRIDE * 2)    // 9216
#define SM_T_HI  0
#define SM_T_LO  (1 * BMATB)
#define SM_T3_HI (2 * BMATB)
#define SM_T3_LO (3 * BMATB)
#define T2STRIDE 68
#define SM_T2    (4 * BMATB)          // fp32 64 x 68
#define SMEM_BYTES (SM_T2 + 64 * T2STRIDE * 4)   // 54272

__device__ __forceinline__ uint32_t smem_u32(const void* p) {
    uint32_t r;
    asm("{ .reg .u64 t; cvta.to.shared.u64 t, %1; cvt.u32.u64 %0, t; }" : "=r"(r) : "l"(p));
    return r;
}
__device__ __forceinline__ void ldsm_x4_t(uint32_t addr, uint32_t* r) {
    asm volatile("ldmatrix.sync.aligned.m8n8.x4.trans.shared.b16 {%0,%1,%2,%3}, [%4];"
        : "=r"(r[0]), "=r"(r[1]), "=r"(r[2]), "=r"(r[3]) : "r"(addr));
}
__device__ __forceinline__ void mma_bf16(float* c, const uint32_t* a, const uint32_t* b) {
    asm volatile("mma.sync.aligned.m16n8k16.row.col.f32.bf16.bf16.f32 "
        "{%0,%1,%2,%3}, {%4,%5,%6,%7}, {%8,%9}, {%0,%1,%2,%3};"
        : "+f"(c[0]), "+f"(c[1]), "+f"(c[2]), "+f"(c[3])
        : "r"(a[0]), "r"(a[1]), "r"(a[2]), "r"(a[3]), "r"(b[0]), "r"(b[1]));
}
__device__ __forceinline__ uint32_t pack2(__nv_bfloat16 x0, __nv_bfloat16 x1) {
    return ((uint32_t)__bfloat16_as_ushort(x1) << 16) | (uint32_t)__bfloat16_as_ushort(x0);
}
__device__ __forceinline__ void split2(float x0, float x1, uint32_t& hw, uint32_t& lw) {
    __nv_bfloat16 h0 = __float2bfloat16(x0);
    __nv_bfloat16 h1 = __float2bfloat16(x1);
    __nv_bfloat16 l0 = __float2bfloat16(x0 - __bfloat162float(h0));
    __nv_bfloat16 l1 = __float2bfloat16(x1 - __bfloat162float(h1));
    hw = pack2(h0, h1);
    lw = pack2(l0, l1);
}
__device__ __forceinline__ float loW(uint32_t w) { return __uint_as_float(w << 16); }
__device__ __forceinline__ float hiW(uint32_t w) { return __uint_as_float(w & 0xFFFF0000u); }

#define SMW(buf, i, j) (*reinterpret_cast<const uint32_t*>(smem + (buf) + ((i) * BSTRIDE + (j)) * 2))

// C[2][8][4] = (Ah+Al)(Bh+Bl): warp w owns rows [32w,32w+32) (mi: 16-row halves).
// tri=true: skip (pp,mi) with 16pp+15 < 32w+16mi (strictly-lower tiles of final product).
__device__ __forceinline__ void mm32x64(const uint32_t sb, const int b_hi, const int b_lo,
                                        const uint32_t Ah[4][2][4], const uint32_t Al[4][2][4],
                                        const int lane, const int w, float C[2][8][4],
                                        const bool tri)
{
    #pragma unroll
    for (int mi = 0; mi < 2; ++mi)
        #pragma unroll
        for (int t = 0; t < 8; ++t)
            #pragma unroll
            for (int r = 0; r < 4; ++r) C[mi][t][r] = 0.0f;

    const int lrow = lane & 15;
    const int lcol8 = 8 * (lane >> 4);

    #pragma unroll
    for (int kc = 0; kc < 4; ++kc) {
        #pragma unroll
        for (int pp = 0; pp < 4; ++pp) {
            if (tri && pp < 2 * w) continue;          // no mi needs this column block
            uint32_t bh[4], bl[4];
            const uint32_t b_off = (uint32_t)(((16 * kc + lrow) * BSTRIDE + 16 * pp + lcol8) * 2);
            ldsm_x4_t(sb + b_hi + b_off, bh);
            ldsm_x4_t(sb + b_lo + b_off, bl);
            #pragma unroll
            for (int mi = 0; mi < 2; ++mi) {
                if (tri && pp < 2 * w + mi) continue;
                mma_bf16(C[mi][2 * pp],     Ah[kc][mi], bh);
                mma_bf16(C[mi][2 * pp + 1], Ah[kc][mi], bh + 2);
                mma_bf16(C[mi][2 * pp],     Ah[kc][mi], bl);
                mma_bf16(C[mi][2 * pp + 1], Ah[kc][mi], bl + 2);
                mma_bf16(C[mi][2 * pp],     Al[kc][mi], bh);
                mma_bf16(C[mi][2 * pp + 1], Al[kc][mi], bh + 2);
            }
        }
    }
}

__device__ __forceinline__ void pack_A(const float C[2][8][4],
                                       uint32_t Ah[4][2][4], uint32_t Al[4][2][4])
{
    #pragma unroll
    for (int kc = 0; kc < 4; ++kc)
        #pragma unroll
        for (int mi = 0; mi < 2; ++mi) {
            split2(C[mi][2 * kc][0],     C[mi][2 * kc][1],     Ah[kc][mi][0], Al[kc][mi][0]);
            split2(C[mi][2 * kc][2],     C[mi][2 * kc][3],     Ah[kc][mi][1], Al[kc][mi][1]);
            split2(C[mi][2 * kc + 1][0], C[mi][2 * kc + 1][1], Ah[kc][mi][2], Al[kc][mi][2]);
            split2(C[mi][2 * kc + 1][2], C[mi][2 * kc + 1][3], Ah[kc][mi][3], Al[kc][mi][3]);
        }
}

// C <- k3*C + k2*T2 + k1*T + k0*I. tri=true restricts to tiles t >= 4w+2mi.
__device__ __forceinline__ void combo(const char* smem, float C[2][8][4],
                                      const float k3, const float k2, const float k1,
                                      const float k0, const int w, const int grp,
                                      const int jb, const bool tri)
{
    #pragma unroll
    for (int mi = 0; mi < 2; ++mi) {
        #pragma unroll
        for (int t = 0; t < 8; ++t) {
            if (tri && t < 4 * w + 2 * mi) continue;
            const int j0 = 8 * t + jb;
            #pragma unroll
            for (int rr = 0; rr < 2; ++rr) {
                const int i = 32 * w + 16 * mi + grp + 8 * rr;
                const uint32_t hw = SMW(SM_T_HI, i, j0);
                const uint32_t lw = SMW(SM_T_LO, i, j0);
                const float2 t2v = *reinterpret_cast<const float2*>(smem + SM_T2 + (i * T2STRIDE + j0) * 4);
                float m0 = k3 * C[mi][t][2 * rr]     + k2 * t2v.x + k1 * (loW(hw) + loW(lw));
                float m1 = k3 * C[mi][t][2 * rr + 1] + k2 * t2v.y + k1 * (hiW(hw) + hiW(lw));
                if (i == j0) m0 += k0;
                if (i == j0 + 1) m1 += k0;
                C[mi][t][2 * rr] = m0;
                C[mi][t][2 * rr + 1] = m1;
            }
        }
    }
}

__global__ void __launch_bounds__(64, 4)
logeig_mma4_kernel(const float* __restrict__ in, float* __restrict__ out, const Coeffs cc)
{
    extern __shared__ __align__(16) char smem[];
    const uint32_t sb = smem_u32(smem);
    const int tid = threadIdx.x;
    const int w = tid >> 5, lane = tid & 31;
    const int grp = lane >> 2, tid4 = lane & 3;
    const int jb = 2 * tid4;
    const size_t mat = blockIdx.x;

    // ---- build T = s1*A + s0*I: one full row per thread ----
    {
        const float* Ag = in + mat * 4096 + (size_t)tid * 64;
        char* hrow = smem + SM_T_HI + tid * BSTRIDE * 2;
        char* lrow = smem + SM_T_LO + tid * BSTRIDE * 2;
        #pragma unroll
        for (int q = 0; q < 16; ++q) {
            const float4 v = *reinterpret_cast<const float4*>(Ag + q * 4);
            float t0 = cc.s1 * v.x, t1 = cc.s1 * v.y, t2 = cc.s1 * v.z, t3 = cc.s1 * v.w;
            if (tid == q * 4 + 0) t0 += cc.s0;
            if (tid == q * 4 + 1) t1 += cc.s0;
            if (tid == q * 4 + 2) t2 += cc.s0;
            if (tid == q * 4 + 3) t3 += cc.s0;
            uint32_t h0, l0, h1, l1;
            split2(t0, t1, h0, l0);
            split2(t2, t3, h1, l1);
            uint2 hv; hv.x = h0; hv.y = h1;
            uint2 lv; lv.x = l0; lv.y = l1;
            *reinterpret_cast<uint2*>(hrow + q * 8) = hv;
            *reinterpret_cast<uint2*>(lrow + q * 8) = lv;
        }
    }
    __syncthreads();

    // ---- A-fragments of T (step0) straight from smem words ----
    uint32_t Ah[4][2][4], Al[4][2][4];
    #pragma unroll
    for (int kc = 0; kc < 4; ++kc)
        #pragma unroll
        for (int mi = 0; mi < 2; ++mi) {
            const int i0 = 32 * w + 16 * mi + grp;
            Ah[kc][mi][0] = SMW(SM_T_HI, i0,     16 * kc + jb);
            Ah[kc][mi][1] = SMW(SM_T_HI, i0 + 8, 16 * kc + jb);
            Ah[kc][mi][2] = SMW(SM_T_HI, i0,     16 * kc + 8 + jb);
            Ah[kc][mi][3] = SMW(SM_T_HI, i0 + 8, 16 * kc + 8 + jb);
            Al[kc][mi][0] = SMW(SM_T_LO, i0,     16 * kc + jb);
            Al[kc][mi][1] = SMW(SM_T_LO, i0 + 8, 16 * kc + jb);
            Al[kc][mi][2] = SMW(SM_T_LO, i0,     16 * kc + 8 + jb);
            Al[kc][mi][3] = SMW(SM_T_LO, i0 + 8, 16 * kc + 8 + jb);
        }

    float C[2][8][4];

    // ---- step0: C = T*T (T2) -> own-position fp32 STS; A <- split(T2). no sync ----
    mm32x64(sb, SM_T_HI, SM_T_LO, Ah, Al, lane, w, C, false);
    #pragma unroll
    for (int mi = 0; mi < 2; ++mi)
        #pragma unroll
        for (int t = 0; t < 8; ++t) {
            const int j0 = 8 * t + jb;
            #pragma unroll
            for (int rr = 0; rr < 2; ++rr) {
                const int i = 32 * w + 16 * mi + grp + 8 * rr;
                float2 v; v.x = C[mi][t][2 * rr]; v.y = C[mi][t][2 * rr + 1];
                *reinterpret_cast<float2*>(smem + SM_T2 + (i * T2STRIDE + j0) * 4) = v;
            }
        }
    pack_A(C, Ah, Al);

    // ---- step1: C = T2*T (T3) -> STS bf16 T3; combo M = a9 C + a8 T2 + a7 T + a6 I ----
    mm32x64(sb, SM_T_HI, SM_T_LO, Ah, Al, lane, w, C, false);
    #pragma unroll
    for (int mi = 0; mi < 2; ++mi)
        #pragma unroll
        for (int t = 0; t < 8; ++t) {
            const int j0 = 8 * t + jb;
            #pragma unroll
            for (int rr = 0; rr < 2; ++rr) {
                const int i = 32 * w + 16 * mi + grp + 8 * rr;
                uint32_t hw, lw;
                split2(C[mi][t][2 * rr], C[mi][t][2 * rr + 1], hw, lw);
                *reinterpret_cast<uint32_t*>(smem + SM_T3_HI + (i * BSTRIDE + j0) * 2) = hw;
                *reinterpret_cast<uint32_t*>(smem + SM_T3_LO + (i * BSTRIDE + j0) * 2) = lw;
            }
        }
    combo(smem, C, cc.a[9], cc.a[8], cc.a[7], cc.a[6], w, grp, jb, false);
    pack_A(C, Ah, Al);
    __syncthreads();   // T3 visible to both warps

    // ---- step2: C = M*T3 ; combo M' = C + a5 T2 + a4 T + a3 I ----
    mm32x64(sb, SM_T3_HI, SM_T3_LO, Ah, Al, lane, w, C, false);
    combo(smem, C, 1.0f, cc.a[5], cc.a[4], cc.a[3], w, grp, jb, false);
    pack_A(C, Ah, Al);
    // no sync: B (T3) unchanged

    // ---- step3: triangle-restricted product + combo ----
    mm32x64(sb, SM_T3_HI, SM_T3_LO, Ah, Al, lane, w, C, true);
    combo(smem, C, 1.0f, cc.a[2], cc.a[1], cc.a[0], w, grp, jb, true);

    // ---- epilogue direct from regs ----
    {
        const float SQ2 = 1.41421356237309515f;
        float* ob = out + mat * 2080;
        #pragma unroll
        for (int mi = 0; mi < 2; ++mi)
            #pragma unroll
            for (int rr = 0; rr < 2; ++rr) {
                const int i = 32 * w + 16 * mi + grp + 8 * rr;
                const int rowbase = i * (129 - i) / 2 - i;
                #pragma unroll
                for (int t = 0; t < 8; ++t) {
                    if (t < 4 * w + 2 * mi) continue;
                    const int j0 = 8 * t + jb;
                    #pragma unroll
                    for (int c = 0; c < 2; ++c) {
                        const int j = j0 + c;
                        if (j >= i) {
                            const float v = fabsf(C[mi][t][2 * rr + c]);
                            ob[rowbase + j] = (i == j) ? v : v * SQ2;
                        }
                    }
                }
            }
    }
}

extern "C" void kernel_launch(void* const* d_in, const int* in_sizes, int n_in,
                              void* d_out, int out_size)
{
    const float* in = (const float*)d_in[0];
    float* out = (float*)d_out;
    const int nmat = in_sizes[0] / 4096;

    // Chebyshev series of log on [a,b] -> monomial coeffs in t (well-conditioned).
    const double a = 0.97, b = 7.0;
    const double mm = 0.5 * (a + b);
    const double wdl = (b - a) / (b + a);
    const double z = (sqrt(1.0 - wdl * wdl) - 1.0) / wdl;

    double c[NDEG + 1];
    c[0] = log(mm) - log(1.0 + z * z);
    double zk = 1.0;
    for (int k = 1; k <= NDEG; ++k) { zk *= z; c[k] = -2.0 * zk / (double)k; }

    double am[NDEG + 1];
    for (int j = 0; j <= NDEG; ++j) am[j] = 0.0;
    {
        double Tm1[NDEG + 1] = {0}, Tk[NDEG + 1] = {0}, Tn[NDEG + 1];
        Tm1[0] = 1.0;
        Tk[1] = 1.0;
        am[0] += c[0] * Tm1[0];
        am[1] += c[1] * Tk[1];
        for (int k = 2; k <= NDEG; ++k) {
            for (int j = 0; j <= NDEG; ++j) Tn[j] = -Tm1[j];
            for (int j = 1; j <= NDEG; ++j) Tn[j] += 2.0 * Tk[j - 1];
            for (int j = 0; j <= NDEG; ++j) { am[j] += c[k] * Tn[j]; Tm1[j] = Tk[j]; Tk[j] = Tn[j]; }
        }
    }

    Coeffs cc;
    for (int j = 0; j <= NDEG; ++j) cc.a[j] = (float)am[j];
    cc.s1 = (float)(2.0 / (b - a));
    cc.s0 = (float)(-(a + b) / (b - a));

    cudaFuncSetAttribute(logeig_mma4_kernel,
                         cudaFuncAttributeMaxDynamicSharedMemorySize, SMEM_BYTES);
    logeig_mma4_kernel<<<nmat, 64, SMEM_BYTES>>>(in, out, cc);
}

// round 8
// speedup vs baseline: 1.1065x; 1.1065x over previous
#include <cuda_runtime.h>
#include <cuda_bf16.h>
#include <math.h>
#include <stdint.h>

#define NDEG 9
struct Coeffs { float a[NDEG + 1]; float s1, s0; };

// smem: bf16 B matrices (T, T3 as hi/lo) + swizzled flat fp32 T2.
#define BSTRIDE 72
#define BMATB   (64 * BSTRIDE * 2)        // 9216
#define SM_T_HI  0
#define SM_T_LO  (1 * BMATB)
#define SM_T3_HI (2 * BMATB)
#define SM_T3_LO (3 * BMATB)
#define SM_T2    (4 * BMATB)              // fp32 64x64, column-pair swizzled
#define SMEM_BYTES (SM_T2 + 64 * 64 * 4)  // 53248

__device__ __forceinline__ uint32_t smem_u32(const void* p) {
    uint32_t r;
    asm("{ .reg .u64 t; cvta.to.shared.u64 t, %1; cvt.u32.u64 %0, t; }" : "=r"(r) : "l"(p));
    return r;
}
__device__ __forceinline__ void ldsm_x4_t(uint32_t addr, uint32_t* r) {
    asm volatile("ldmatrix.sync.aligned.m8n8.x4.trans.shared.b16 {%0,%1,%2,%3}, [%4];"
        : "=r"(r[0]), "=r"(r[1]), "=r"(r[2]), "=r"(r[3]) : "r"(addr));
}
__device__ __forceinline__ void mma_bf16(float* c, const uint32_t* a, const uint32_t* b) {
    asm volatile("mma.sync.aligned.m16n8k16.row.col.f32.bf16.bf16.f32 "
        "{%0,%1,%2,%3}, {%4,%5,%6,%7}, {%8,%9}, {%0,%1,%2,%3};"
        : "+f"(c[0]), "+f"(c[1]), "+f"(c[2]), "+f"(c[3])
        : "r"(a[0]), "r"(a[1]), "r"(a[2]), "r"(a[3]), "r"(b[0]), "r"(b[1]));
}
__device__ __forceinline__ uint32_t pack2(__nv_bfloat16 x0, __nv_bfloat16 x1) {
    return ((uint32_t)__bfloat16_as_ushort(x1) << 16) | (uint32_t)__bfloat16_as_ushort(x0);
}
__device__ __forceinline__ void split2(float x0, float x1, uint32_t& hw, uint32_t& lw) {
    __nv_bfloat16 h0 = __float2bfloat16(x0);
    __nv_bfloat16 h1 = __float2bfloat16(x1);
    __nv_bfloat16 l0 = __float2bfloat16(x0 - __bfloat162float(h0));
    __nv_bfloat16 l1 = __float2bfloat16(x1 - __bfloat162float(h1));
    hw = pack2(h0, h1);
    lw = pack2(l0, l1);
}
__device__ __forceinline__ float loW(uint32_t w) { return __uint_as_float(w << 16); }
__device__ __forceinline__ float hiW(uint32_t w) { return __uint_as_float(w & 0xFFFF0000u); }
__device__ __forceinline__ void sts16(uint32_t addr, unsigned short v) {
    asm volatile("st.shared.u16 [%0], %1;" :: "r"(addr), "h"(v));
}

#define SMW(buf, i, j) (*reinterpret_cast<const uint32_t*>(smem + (buf) + ((i) * BSTRIDE + (j)) * 2))

// byte offset of fp32 T2 element (i,j): per-row column-pair swizzle, float2-safe
__device__ __forceinline__ uint32_t t2_woff(int i, int j) {
    const int up = (((j >> 1) + 4 * (i & 7)) & 31);
    return (uint32_t)((i * 64 + 2 * up + (j & 1)) * 4);
}

// C = (Ah+Al)(Bh+Bl): A frags in regs, B via ldmatrix.trans; skip column blocks pp < pp0.
__device__ __forceinline__ void mm64_regA(const uint32_t sb, const int b_hi, const int b_lo,
                                          const uint32_t Ah[4][4], const uint32_t Al[4][4],
                                          const int lane, float C[8][4], const int pp0)
{
    #pragma unroll
    for (int t = 0; t < 8; ++t)
        #pragma unroll
        for (int r = 0; r < 4; ++r) C[t][r] = 0.0f;

    const int lrow = lane & 15;
    const int lcol8 = 8 * (lane >> 4);

    #pragma unroll
    for (int kc = 0; kc < 4; ++kc) {
        #pragma unroll
        for (int pp = 0; pp < 4; ++pp) {
            if (pp < pp0) continue;
            uint32_t bh[4], bl[4];
            const uint32_t b_off = (uint32_t)(((16 * kc + lrow) * BSTRIDE + 16 * pp + lcol8) * 2);
            ldsm_x4_t(sb + b_hi + b_off, bh);
            ldsm_x4_t(sb + b_lo + b_off, bl);
            mma_bf16(C[2 * pp],     Ah[kc], bh);
            mma_bf16(C[2 * pp + 1], Ah[kc], bh + 2);
            mma_bf16(C[2 * pp],     Ah[kc], bl);
            mma_bf16(C[2 * pp + 1], Ah[kc], bl + 2);
            mma_bf16(C[2 * pp],     Al[kc], bh);
            mma_bf16(C[2 * pp + 1], Al[kc], bh + 2);
        }
    }
}

__device__ __forceinline__ void pack_A(const float C[8][4], uint32_t Ah[4][4], uint32_t Al[4][4])
{
    #pragma unroll
    for (int kc = 0; kc < 4; ++kc) {
        split2(C[2 * kc][0],     C[2 * kc][1],     Ah[kc][0], Al[kc][0]);
        split2(C[2 * kc][2],     C[2 * kc][3],     Ah[kc][1], Al[kc][1]);
        split2(C[2 * kc + 1][0], C[2 * kc + 1][1], Ah[kc][2], Al[kc][2]);
        split2(C[2 * kc + 1][2], C[2 * kc + 1][3], Ah[kc][3], Al[kc][3]);
    }
}

// C <- k3*C + k2*T2 + k1*T + k0*I, tiles t >= t0 only (swizzled T2 reads).
__device__ __forceinline__ void combo(const char* smem, float C[8][4],
                                      const float k3, const float k2, const float k1,
                                      const float k0, const int ib, const int jb,
                                      const int t0)
{
    #pragma unroll
    for (int t = 0; t < 8; ++t) {
        if (t < t0) continue;
        const int j0 = 8 * t + jb;
        #pragma unroll
        for (int rr = 0; rr < 2; ++rr) {
            const int i = ib + 8 * rr;
            const uint32_t hw = SMW(SM_T_HI, i, j0);
            const uint32_t lw = SMW(SM_T_LO, i, j0);
            const float2 t2v = *reinterpret_cast<const float2*>(smem + SM_T2 + t2_woff(i, j0));
            float m0 = k3 * C[t][2 * rr]     + k2 * t2v.x + k1 * (loW(hw) + loW(lw));
            float m1 = k3 * C[t][2 * rr + 1] + k2 * t2v.y + k1 * (hiW(hw) + hiW(lw));
            if (i == j0) m0 += k0;
            if (i == j0 + 1) m1 += k0;
            C[t][2 * rr] = m0;
            C[t][2 * rr + 1] = m1;
        }
    }
}

__global__ void __launch_bounds__(128, 4)
logeig_mma5_kernel(const float* __restrict__ in, float* __restrict__ out, const Coeffs cc)
{
    extern __shared__ __align__(16) char smem[];
    const uint32_t sb = smem_u32(smem);
    const int tid = threadIdx.x;
    const int w = tid >> 5, lane = tid & 31;
    const int grp = lane >> 2, tid4 = lane & 3;
    const int ib = 16 * w + grp;
    const int jb = 2 * tid4;
    const size_t mat = blockIdx.x;

    // ---- build T = s1*A + s0*I as bf16 hi/lo in smem ----
    {
        const float* Ag = in + mat * 4096 + (size_t)(tid >> 1) * 64 + (tid & 1) * 32;
        char* hrow = smem + SM_T_HI + ((tid >> 1) * BSTRIDE + (tid & 1) * 32) * 2;
        char* lrow = smem + SM_T_LO + ((tid >> 1) * BSTRIDE + (tid & 1) * 32) * 2;
        const int di = (tid >> 1) - (tid & 1) * 32;
        #pragma unroll
        for (int q = 0; q < 8; ++q) {
            const float4 v = *reinterpret_cast<const float4*>(Ag + q * 4);
            float t0 = cc.s1 * v.x, t1 = cc.s1 * v.y, t2 = cc.s1 * v.z, t3 = cc.s1 * v.w;
            if (di == q * 4 + 0) t0 += cc.s0;
            if (di == q * 4 + 1) t1 += cc.s0;
            if (di == q * 4 + 2) t2 += cc.s0;
            if (di == q * 4 + 3) t3 += cc.s0;
            uint32_t h0, l0, h1, l1;
            split2(t0, t1, h0, l0);
            split2(t2, t3, h1, l1);
            reinterpret_cast<uint32_t*>(hrow)[2 * q] = h0;
            reinterpret_cast<uint32_t*>(hrow)[2 * q + 1] = h1;
            reinterpret_cast<uint32_t*>(lrow)[2 * q] = l0;
            reinterpret_cast<uint32_t*>(lrow)[2 * q + 1] = l1;
        }
    }
    __syncthreads();

    // ---- A-fragments of T (step0) ----
    uint32_t Ah[4][4], Al[4][4];
    #pragma unroll
    for (int t = 0; t < 8; ++t) {
        const int j0 = 8 * t + jb;
        #pragma unroll
        for (int rr = 0; rr < 2; ++rr) {
            const int i = ib + 8 * rr;
            Ah[t >> 1][(t & 1) * 2 + rr] = SMW(SM_T_HI, i, j0);
            Al[t >> 1][(t & 1) * 2 + rr] = SMW(SM_T_LO, i, j0);
        }
    }

    float C[8][4];

    // ---- step0: C = T*T (T2), upper column blocks only; own+mirrored fp32 STS ----
    mm64_regA(sb, SM_T_HI, SM_T_LO, Ah, Al, lane, C, w);
    #pragma unroll
    for (int t = 0; t < 8; ++t) {
        if (t < 2 * w) continue;
        const int j0 = 8 * t + jb;
        #pragma unroll
        for (int rr = 0; rr < 2; ++rr) {
            const int i = ib + 8 * rr;
            float2 v; v.x = C[t][2 * rr]; v.y = C[t][2 * rr + 1];
            *reinterpret_cast<float2*>(smem + SM_T2 + t2_woff(i, j0)) = v;
            if (j0 > i)     *reinterpret_cast<float*>(smem + SM_T2 + t2_woff(j0, i))     = v.x;
            if (j0 + 1 > i) *reinterpret_cast<float*>(smem + SM_T2 + t2_woff(j0 + 1, i)) = v.y;
        }
    }
    __syncthreads();

    // ---- step1 A-fragments: kc<w from mirrored T2 smem, else from C ----
    #pragma unroll
    for (int kc = 0; kc < 4; ++kc) {
        if (kc < w) {
            #pragma unroll
            for (int q = 0; q < 4; ++q) {
                const int i = ib + 8 * (q & 1);
                const int j = 16 * kc + 8 * (q >> 1) + jb;
                const float2 v = *reinterpret_cast<const float2*>(smem + SM_T2 + t2_woff(i, j));
                split2(v.x, v.y, Ah[kc][q], Al[kc][q]);
            }
        } else {
            split2(C[2 * kc][0],     C[2 * kc][1],     Ah[kc][0], Al[kc][0]);
            split2(C[2 * kc][2],     C[2 * kc][3],     Ah[kc][1], Al[kc][1]);
            split2(C[2 * kc + 1][0], C[2 * kc + 1][1], Ah[kc][2], Al[kc][2]);
            split2(C[2 * kc + 1][2], C[2 * kc + 1][3], Ah[kc][3], Al[kc][3]);
        }
    }

    // ---- step1: C = T2*T (T3), upper blocks only; STS T3 own + mirrored bf16 ----
    mm64_regA(sb, SM_T_HI, SM_T_LO, Ah, Al, lane, C, w);
    #pragma unroll
    for (int t = 0; t < 8; ++t) {
        if (t < 2 * w) continue;
        const int j0 = 8 * t + jb;
        #pragma unroll
        for (int rr = 0; rr < 2; ++rr) {
            const int i = ib + 8 * rr;
            uint32_t hw, lw;
            split2(C[t][2 * rr], C[t][2 * rr + 1], hw, lw);
            *reinterpret_cast<uint32_t*>(smem + SM_T3_HI + (i * BSTRIDE + j0) * 2) = hw;
            *reinterpret_cast<uint32_t*>(smem + SM_T3_LO + (i * BSTRIDE + j0) * 2) = lw;
            if (j0 > i) {
                sts16(sb + SM_T3_HI + (j0 * BSTRIDE + i) * 2, (unsigned short)(hw & 0xFFFF));
                sts16(sb + SM_T3_LO + (j0 * BSTRIDE + i) * 2, (unsigned short)(lw & 0xFFFF));
            }
            if (j0 + 1 > i) {
                sts16(sb + SM_T3_HI + ((j0 + 1) * BSTRIDE + i) * 2, (unsigned short)(hw >> 16));
                sts16(sb + SM_T3_LO + ((j0 + 1) * BSTRIDE + i) * 2, (unsigned short)(lw >> 16));
            }
        }
    }
    __syncthreads();

    // ---- M = a9*T3 + a8*T2 + a7*T + a6*I: lower tiles from smem, upper from regs ----
    #pragma unroll
    for (int t = 0; t < 8; ++t) {
        const int j0 = 8 * t + jb;
        #pragma unroll
        for (int rr = 0; rr < 2; ++rr) {
            const int i = ib + 8 * rr;
            const uint32_t thw = SMW(SM_T_HI, i, j0);
            const uint32_t tlw = SMW(SM_T_LO, i, j0);
            const float2 t2v = *reinterpret_cast<const float2*>(smem + SM_T2 + t2_woff(i, j0));
            if (t < 2 * w) {      // strictly lower: T3 via mirror (no diagonal here)
                const uint32_t h3 = SMW(SM_T3_HI, i, j0);
                const uint32_t l3 = SMW(SM_T3_LO, i, j0);
                C[t][2 * rr]     = cc.a[9] * (loW(h3) + loW(l3)) + cc.a[8] * t2v.x + cc.a[7] * (loW(thw) + loW(tlw));
                C[t][2 * rr + 1] = cc.a[9] * (hiW(h3) + hiW(l3)) + cc.a[8] * t2v.y + cc.a[7] * (hiW(thw) + hiW(tlw));
            } else {
                float m0 = cc.a[9] * C[t][2 * rr]     + cc.a[8] * t2v.x + cc.a[7] * (loW(thw) + loW(tlw));
                float m1 = cc.a[9] * C[t][2 * rr + 1] + cc.a[8] * t2v.y + cc.a[7] * (hiW(thw) + hiW(tlw));
                if (i == j0) m0 += cc.a[6];
                if (i == j0 + 1) m1 += cc.a[6];
                C[t][2 * rr] = m0;
                C[t][2 * rr + 1] = m1;
            }
        }
    }
    pack_A(C, Ah, Al);

    // ---- step2: C = M*T3 (full); M' = C + a5*T2 + a4*T + a3*I ----
    mm64_regA(sb, SM_T3_HI, SM_T3_LO, Ah, Al, lane, C, 0);
    combo(smem, C, 1.0f, cc.a[5], cc.a[4], cc.a[3], ib, jb, 0);
    pack_A(C, Ah, Al);

    // ---- step3: triangle-restricted; F = C + a2*T2 + a1*T + a0*I ----
    mm64_regA(sb, SM_T3_HI, SM_T3_LO, Ah, Al, lane, C, w);
    combo(smem, C, 1.0f, cc.a[2], cc.a[1], cc.a[0], ib, jb, 2 * w);

    // ---- epilogue direct from regs ----
    {
        const float SQ2 = 1.41421356237309515f;
        float* ob = out + mat * 2080;
        #pragma unroll
        for (int rr = 0; rr < 2; ++rr) {
            const int i = ib + 8 * rr;
            const int rowbase = i * (129 - i) / 2 - i;
            #pragma unroll
            for (int t = 0; t < 8; ++t) {
                if (t < 2 * w) continue;
                const int j0 = 8 * t + jb;
                #pragma unroll
                for (int c = 0; c < 2; ++c) {
                    const int j = j0 + c;
                    if (j >= i) {
                        const float v = fabsf(C[t][2 * rr + c]);
                        ob[rowbase + j] = (i == j) ? v : v * SQ2;
                    }
                }
            }
        }
    }
}

extern "C" void kernel_launch(void* const* d_in, const int* in_sizes, int n_in,
                              void* d_out, int out_size)
{
    const float* in = (const float*)d_in[0];
    float* out = (float*)d_out;
    const int nmat = in_sizes[0] / 4096;

    // Chebyshev series of log on [a,b] -> monomial coeffs in t (well-conditioned).
    const double a = 0.97, b = 7.0;
    const double mm = 0.5 * (a + b);
    const double wdl = (b - a) / (b + a);
    const double z = (sqrt(1.0 - wdl * wdl) - 1.0) / wdl;

    double c[NDEG + 1];
    c[0] = log(mm) - log(1.0 + z * z);
    double zk = 1.0;
    for (int k = 1; k <= NDEG; ++k) { zk *= z; c[k] = -2.0 * zk / (double)k; }

    double am[NDEG + 1];
    for (int j = 0; j <= NDEG; ++j) am[j] = 0.0;
    {
        double Tm1[NDEG + 1] = {0}, Tk[NDEG + 1] = {0}, Tn[NDEG + 1];
        Tm1[0] = 1.0;
        Tk[1] = 1.0;
        am[0] += c[0] * Tm1[0];
        am[1] += c[1] * Tk[1];
        for (int k = 2; k <= NDEG; ++k) {
            for (int j = 0; j <= NDEG; ++j) Tn[j] = -Tm1[j];
            for (int j = 1; j <= NDEG; ++j) Tn[j] += 2.0 * Tk[j - 1];
            for (int j = 0; j <= NDEG; ++j) { am[j] += c[k] * Tn[j]; Tm1[j] = Tk[j]; Tk[j] = Tn[j]; }
        }
    }

    Coeffs cc;
    for (int j = 0; j <= NDEG; ++j) cc.a[j] = (float)am[j];
    cc.s1 = (float)(2.0 / (b - a));
    cc.s0 = (float)(-(a + b) / (b - a));

    cudaFuncSetAttribute(logeig_mma5_kernel,
                         cudaFuncAttributeMaxDynamicSharedMemorySize, SMEM_BYTES);
    logeig_mma5_kernel<<<nmat, 128, SMEM_BYTES>>>(in, out, cc);
}

// round 9
// speedup vs baseline: 1.2464x; 1.1264x over previous
#include <cuda_runtime.h>
#include <cuda_bf16.h>
#include <math.h>
#include <stdint.h>

#define NDEG 9
struct Coeffs { float a[NDEG + 1]; float s1, s0; };

// smem: bf16 B matrices (T, T3 as hi/lo) + swizzled flat fp32 T2.
#define BSTRIDE 72
#define BMATB   (64 * BSTRIDE * 2)        // 9216
#define SM_T_HI  0
#define SM_T_LO  (1 * BMATB)
#define SM_T3_HI (2 * BMATB)
#define SM_T3_LO (3 * BMATB)
#define SM_T2    (4 * BMATB)              // fp32 64x64, column-pair swizzled
#define SMEM_BYTES (SM_T2 + 64 * 64 * 4)  // 53248

__device__ __forceinline__ uint32_t smem_u32(const void* p) {
    uint32_t r;
    asm("{ .reg .u64 t; cvta.to.shared.u64 t, %1; cvt.u32.u64 %0, t; }" : "=r"(r) : "l"(p));
    return r;
}
__device__ __forceinline__ void ldsm_x4_t(uint32_t addr, uint32_t* r) {
    asm volatile("ldmatrix.sync.aligned.m8n8.x4.trans.shared.b16 {%0,%1,%2,%3}, [%4];"
        : "=r"(r[0]), "=r"(r[1]), "=r"(r[2]), "=r"(r[3]) : "r"(addr));
}
__device__ __forceinline__ void mma_bf16(float* c, const uint32_t* a, const uint32_t* b) {
    asm volatile("mma.sync.aligned.m16n8k16.row.col.f32.bf16.bf16.f32 "
        "{%0,%1,%2,%3}, {%4,%5,%6,%7}, {%8,%9}, {%0,%1,%2,%3};"
        : "+f"(c[0]), "+f"(c[1]), "+f"(c[2]), "+f"(c[3])
        : "r"(a[0]), "r"(a[1]), "r"(a[2]), "r"(a[3]), "r"(b[0]), "r"(b[1]));
}
__device__ __forceinline__ float loW(uint32_t w) { return __uint_as_float(w << 16); }
__device__ __forceinline__ float hiW(uint32_t w) { return __uint_as_float(w & 0xFFFF0000u); }

// fast split: one packed cvt for hi pair, exact residual, one packed cvt for lo pair
__device__ __forceinline__ void split2(float x0, float x1, uint32_t& hw, uint32_t& lw) {
    asm("cvt.rn.bf16x2.f32 %0, %1, %2;" : "=r"(hw) : "f"(x1), "f"(x0));
    const float l0 = x0 - loW(hw);
    const float l1 = x1 - hiW(hw);
    asm("cvt.rn.bf16x2.f32 %0, %1, %2;" : "=r"(lw) : "f"(l1), "f"(l0));
}

#define SMW(buf, i, j) (*reinterpret_cast<const uint32_t*>(smem + (buf) + ((i) * BSTRIDE + (j)) * 2))

// byte offset of fp32 T2 element (i,j): per-row column-pair swizzle, float2-safe,
// conflict-free at fragment access pattern (banks = tid4 + 4*grp).
__device__ __forceinline__ uint32_t t2_woff(int i, int j) {
    const int up = (((j >> 1) + 4 * (i & 7)) & 31);
    return (uint32_t)((i * 64 + 2 * up + (j & 1)) * 4);
}

// C = (Ah+Al)(Bh+Bl): A frags in regs, B via ldmatrix.trans; skip column blocks pp < pp0.
__device__ __forceinline__ void mm64_regA(const uint32_t sb, const int b_hi, const int b_lo,
                                          const uint32_t Ah[4][4], const uint32_t Al[4][4],
                                          const int lane, float C[8][4], const int pp0)
{
    #pragma unroll
    for (int t = 0; t < 8; ++t)
        #pragma unroll
        for (int r = 0; r < 4; ++r) C[t][r] = 0.0f;

    const int lrow = lane & 15;
    const int lcol8 = 8 * (lane >> 4);

    #pragma unroll
    for (int kc = 0; kc < 4; ++kc) {
        #pragma unroll
        for (int pp = 0; pp < 4; ++pp) {
            if (pp < pp0) continue;
            uint32_t bh[4], bl[4];
            const uint32_t b_off = (uint32_t)(((16 * kc + lrow) * BSTRIDE + 16 * pp + lcol8) * 2);
            ldsm_x4_t(sb + b_hi + b_off, bh);
            ldsm_x4_t(sb + b_lo + b_off, bl);
            mma_bf16(C[2 * pp],     Ah[kc], bh);
            mma_bf16(C[2 * pp + 1], Ah[kc], bh + 2);
            mma_bf16(C[2 * pp],     Ah[kc], bl);
            mma_bf16(C[2 * pp + 1], Ah[kc], bl + 2);
            mma_bf16(C[2 * pp],     Al[kc], bh);
            mma_bf16(C[2 * pp + 1], Al[kc], bh + 2);
        }
    }
}

__device__ __forceinline__ void pack_A(const float C[8][4], uint32_t Ah[4][4], uint32_t Al[4][4])
{
    #pragma unroll
    for (int kc = 0; kc < 4; ++kc) {
        split2(C[2 * kc][0],     C[2 * kc][1],     Ah[kc][0], Al[kc][0]);
        split2(C[2 * kc][2],     C[2 * kc][3],     Ah[kc][1], Al[kc][1]);
        split2(C[2 * kc + 1][0], C[2 * kc + 1][1], Ah[kc][2], Al[kc][2]);
        split2(C[2 * kc + 1][2], C[2 * kc + 1][3], Ah[kc][3], Al[kc][3]);
    }
}

// C <- k3*C + k2*T2 + k1*T + k0*I, tiles t >= t0 only (swizzled T2 reads).
__device__ __forceinline__ void combo(const char* smem, float C[8][4],
                                      const float k3, const float k2, const float k1,
                                      const float k0, const int ib, const int jb,
                                      const int t0)
{
    #pragma unroll
    for (int t = 0; t < 8; ++t) {
        if (t < t0) continue;
        const int j0 = 8 * t + jb;
        #pragma unroll
        for (int rr = 0; rr < 2; ++rr) {
            const int i = ib + 8 * rr;
            const uint32_t hw = SMW(SM_T_HI, i, j0);
            const uint32_t lw = SMW(SM_T_LO, i, j0);
            const float2 t2v = *reinterpret_cast<const float2*>(smem + SM_T2 + t2_woff(i, j0));
            float m0 = k3 * C[t][2 * rr]     + k2 * t2v.x + k1 * (loW(hw) + loW(lw));
            float m1 = k3 * C[t][2 * rr + 1] + k2 * t2v.y + k1 * (hiW(hw) + hiW(lw));
            if (i == j0) m0 += k0;
            if (i == j0 + 1) m1 += k0;
            C[t][2 * rr] = m0;
            C[t][2 * rr + 1] = m1;
        }
    }
}

__global__ void __launch_bounds__(128, 4)
logeig_mma6_kernel(const float* __restrict__ in, float* __restrict__ out, const Coeffs cc)
{
    extern __shared__ __align__(16) char smem[];
    const uint32_t sb = smem_u32(smem);
    const int tid = threadIdx.x;
    const int w = tid >> 5, lane = tid & 31;
    const int grp = lane >> 2, tid4 = lane & 3;
    const int ib = 16 * w + grp;
    const int jb = 2 * tid4;
    const size_t mat = blockIdx.x;

    // ---- build T = s1*A + s0*I as bf16 hi/lo in smem ----
    {
        const float* Ag = in + mat * 4096 + (size_t)(tid >> 1) * 64 + (tid & 1) * 32;
        char* hrow = smem + SM_T_HI + ((tid >> 1) * BSTRIDE + (tid & 1) * 32) * 2;
        char* lrow = smem + SM_T_LO + ((tid >> 1) * BSTRIDE + (tid & 1) * 32) * 2;
        const int di = (tid >> 1) - (tid & 1) * 32;
        #pragma unroll
        for (int q = 0; q < 8; ++q) {
            const float4 v = *reinterpret_cast<const float4*>(Ag + q * 4);
            float t0 = cc.s1 * v.x, t1 = cc.s1 * v.y, t2 = cc.s1 * v.z, t3 = cc.s1 * v.w;
            if (di == q * 4 + 0) t0 += cc.s0;
            if (di == q * 4 + 1) t1 += cc.s0;
            if (di == q * 4 + 2) t2 += cc.s0;
            if (di == q * 4 + 3) t3 += cc.s0;
            uint32_t h0, l0, h1, l1;
            split2(t0, t1, h0, l0);
            split2(t2, t3, h1, l1);
            reinterpret_cast<uint32_t*>(hrow)[2 * q] = h0;
            reinterpret_cast<uint32_t*>(hrow)[2 * q + 1] = h1;
            reinterpret_cast<uint32_t*>(lrow)[2 * q] = l0;
            reinterpret_cast<uint32_t*>(lrow)[2 * q + 1] = l1;
        }
    }
    __syncthreads();

    // ---- A-fragments of T (step0) straight from smem words ----
    uint32_t Ah[4][4], Al[4][4];
    #pragma unroll
    for (int t = 0; t < 8; ++t) {
        const int j0 = 8 * t + jb;
        #pragma unroll
        for (int rr = 0; rr < 2; ++rr) {
            const int i = ib + 8 * rr;
            Ah[t >> 1][(t & 1) * 2 + rr] = SMW(SM_T_HI, i, j0);
            Al[t >> 1][(t & 1) * 2 + rr] = SMW(SM_T_LO, i, j0);
        }
    }

    float C[8][4];

    // ---- step0: C = T*T (T2) -> own-position swizzled fp32 STS; A <- split(T2). no sync ----
    mm64_regA(sb, SM_T_HI, SM_T_LO, Ah, Al, lane, C, 0);
    #pragma unroll
    for (int t = 0; t < 8; ++t) {
        const int j0 = 8 * t + jb;
        #pragma unroll
        for (int rr = 0; rr < 2; ++rr) {
            const int i = ib + 8 * rr;
            float2 v; v.x = C[t][2 * rr]; v.y = C[t][2 * rr + 1];
            *reinterpret_cast<float2*>(smem + SM_T2 + t2_woff(i, j0)) = v;
        }
    }
    pack_A(C, Ah, Al);

    // ---- step1: C = T2*T (T3) -> STS bf16 T3; combo M = a9 C + a8 T2 + a7 T + a6 I ----
    mm64_regA(sb, SM_T_HI, SM_T_LO, Ah, Al, lane, C, 0);
    #pragma unroll
    for (int t = 0; t < 8; ++t) {
        const int j0 = 8 * t + jb;
        #pragma unroll
        for (int rr = 0; rr < 2; ++rr) {
            const int i = ib + 8 * rr;
            uint32_t hw, lw;
            split2(C[t][2 * rr], C[t][2 * rr + 1], hw, lw);
            *reinterpret_cast<uint32_t*>(smem + SM_T3_HI + (i * BSTRIDE + j0) * 2) = hw;
            *reinterpret_cast<uint32_t*>(smem + SM_T3_LO + (i * BSTRIDE + j0) * 2) = lw;
        }
    }
    combo(smem, C, cc.a[9], cc.a[8], cc.a[7], cc.a[6], ib, jb, 0);
    pack_A(C, Ah, Al);
    __syncthreads();   // T3 visible to all warps

    // ---- step2: C = M*T3 ; combo M' = C + a5 T2 + a4 T + a3 I ----
    mm64_regA(sb, SM_T3_HI, SM_T3_LO, Ah, Al, lane, C, 0);
    combo(smem, C, 1.0f, cc.a[5], cc.a[4], cc.a[3], ib, jb, 0);
    pack_A(C, Ah, Al);
    // no sync: B (T3) unchanged

    // ---- step3: only column tiles >= warp's diagonal block ----
    mm64_regA(sb, SM_T3_HI, SM_T3_LO, Ah, Al, lane, C, w);
    combo(smem, C, 1.0f, cc.a[2], cc.a[1], cc.a[0], ib, jb, 2 * w);

    // ---- epilogue direct from regs ----
    {
        const float SQ2 = 1.41421356237309515f;
        float* ob = out + mat * 2080;
        #pragma unroll
        for (int rr = 0; rr < 2; ++rr) {
            const int i = ib + 8 * rr;
            const int rowbase = i * (129 - i) / 2 - i;
            #pragma unroll
            for (int t = 0; t < 8; ++t) {
                if (t < 2 * w) continue;
                const int j0 = 8 * t + jb;
                #pragma unroll
                for (int c = 0; c < 2; ++c) {
                    const int j = j0 + c;
                    if (j >= i) {
                        const float v = fabsf(C[t][2 * rr + c]);
                        ob[rowbase + j] = (i == j) ? v : v * SQ2;
                    }
                }
            }
        }
    }
}

extern "C" void kernel_launch(void* const* d_in, const int* in_sizes, int n_in,
                              void* d_out, int out_size)
{
    const float* in = (const float*)d_in[0];
    float* out = (float*)d_out;
    const int nmat = in_sizes[0] / 4096;

    // Chebyshev series of log on [a,b] -> monomial coeffs in t (well-conditioned).
    const double a = 0.97, b = 7.0;
    const double mm = 0.5 * (a + b);
    const double wdl = (b - a) / (b + a);
    const double z = (sqrt(1.0 - wdl * wdl) - 1.0) / wdl;

    double c[NDEG + 1];
    c[0] = log(mm) - log(1.0 + z * z);
    double zk = 1.0;
    for (int k = 1; k <= NDEG; ++k) { zk *= z; c[k] = -2.0 * zk / (double)k; }

    double am[NDEG + 1];
    for (int j = 0; j <= NDEG; ++j) am[j] = 0.0;
    {
        double Tm1[NDEG + 1] = {0}, Tk[NDEG + 1] = {0}, Tn[NDEG + 1];
        Tm1[0] = 1.0;
        Tk[1] = 1.0;
        am[0] += c[0] * Tm1[0];
        am[1] += c[1] * Tk[1];
        for (int k = 2; k <= NDEG; ++k) {
            for (int j = 0; j <= NDEG; ++j) Tn[j] = -Tm1[j];
            for (int j = 1; j <= NDEG; ++j) Tn[j] += 2.0 * Tk[j - 1];
            for (int j = 0; j <= NDEG; ++j) { am[j] += c[k] * Tn[j]; Tm1[j] = Tk[j]; Tk[j] = Tn[j]; }
        }
    }

    Coeffs cc;
    for (int j = 0; j <= NDEG; ++j) cc.a[j] = (float)am[j];
    cc.s1 = (float)(2.0 / (b - a));
    cc.s0 = (float)(-(a + b) / (b - a));

    cudaFuncSetAttribute(logeig_mma6_kernel,
                         cudaFuncAttributeMaxDynamicSharedMemorySize, SMEM_BYTES);
    logeig_mma6_kernel<<<nmat, 128, SMEM_BYTES>>>(in, out, cc);
}

// round 10
// speedup vs baseline: 1.2815x; 1.0282x over previous
#include <cuda_runtime.h>
#include <cuda_bf16.h>
#include <cuda_fp16.h>
#include <math.h>
#include <stdint.h>

#define NDEG 9
struct Coeffs { float a[NDEG + 1]; float s1, s0; };

// smem: bf16 B matrices (T, T3 as hi/lo) + swizzled fp16 T2.
#define BSTRIDE 72
#define BMATB   (64 * BSTRIDE * 2)        // 9216
#define SM_T_HI  0
#define SM_T_LO  (1 * BMATB)
#define SM_T3_HI (2 * BMATB)
#define SM_T3_LO (3 * BMATB)
#define SM_T2    (4 * BMATB)              // fp16 64x64, word-swizzled (8192 B)
#define SMEM_BYTES (SM_T2 + 64 * 32 * 4)  // 45056

__device__ __forceinline__ uint32_t smem_u32(const void* p) {
    uint32_t r;
    asm("{ .reg .u64 t; cvta.to.shared.u64 t, %1; cvt.u32.u64 %0, t; }" : "=r"(r) : "l"(p));
    return r;
}
__device__ __forceinline__ void ldsm_x4(uint32_t addr, uint32_t* r) {
    asm volatile("ldmatrix.sync.aligned.m8n8.x4.shared.b16 {%0,%1,%2,%3}, [%4];"
        : "=r"(r[0]), "=r"(r[1]), "=r"(r[2]), "=r"(r[3]) : "r"(addr));
}
__device__ __forceinline__ void ldsm_x4_t(uint32_t addr, uint32_t* r) {
    asm volatile("ldmatrix.sync.aligned.m8n8.x4.trans.shared.b16 {%0,%1,%2,%3}, [%4];"
        : "=r"(r[0]), "=r"(r[1]), "=r"(r[2]), "=r"(r[3]) : "r"(addr));
}
__device__ __forceinline__ void mma_bf16(float* c, const uint32_t* a, const uint32_t* b) {
    asm volatile("mma.sync.aligned.m16n8k16.row.col.f32.bf16.bf16.f32 "
        "{%0,%1,%2,%3}, {%4,%5,%6,%7}, {%8,%9}, {%0,%1,%2,%3};"
        : "+f"(c[0]), "+f"(c[1]), "+f"(c[2]), "+f"(c[3])
        : "r"(a[0]), "r"(a[1]), "r"(a[2]), "r"(a[3]), "r"(b[0]), "r"(b[1]));
}
__device__ __forceinline__ float loW(uint32_t w) { return __uint_as_float(w << 16); }
__device__ __forceinline__ float hiW(uint32_t w) { return __uint_as_float(w & 0xFFFF0000u); }

// fast split: packed cvt for hi pair, exact residual, packed cvt for lo pair
__device__ __forceinline__ void split2(float x0, float x1, uint32_t& hw, uint32_t& lw) {
    asm("cvt.rn.bf16x2.f32 %0, %1, %2;" : "=r"(hw) : "f"(x1), "f"(x0));
    const float l0 = x0 - loW(hw);
    const float l1 = x1 - hiW(hw);
    asm("cvt.rn.bf16x2.f32 %0, %1, %2;" : "=r"(lw) : "f"(l1), "f"(l0));
}

#define SMW(buf, i, j) (*reinterpret_cast<const uint32_t*>(smem + (buf) + ((i) * BSTRIDE + (j)) * 2))

// byte offset of fp16 T2 word holding (i,j),(i,j+1): word-level swizzle,
// conflict-free at fragment pattern (bank = 4*grp + 4*t + tid4, all distinct).
__device__ __forceinline__ uint32_t t2h_off(int i, int j) {
    const int up = (((j >> 1) + 4 * (i & 7)) & 31);
    return (uint32_t)((i * 32 + up) * 4);
}

// C = (Ah+Al)(Bh+Bl): A frags in regs, B via ldmatrix.trans; skip column blocks pp < pp0.
__device__ __forceinline__ void mm64_regA(const uint32_t sb, const int b_hi, const int b_lo,
                                          const uint32_t Ah[4][4], const uint32_t Al[4][4],
                                          const int lane, float C[8][4], const int pp0)
{
    #pragma unroll
    for (int t = 0; t < 8; ++t)
        #pragma unroll
        for (int r = 0; r < 4; ++r) C[t][r] = 0.0f;

    const int lrow = lane & 15;
    const int lcol8 = 8 * (lane >> 4);

    #pragma unroll
    for (int kc = 0; kc < 4; ++kc) {
        #pragma unroll
        for (int pp = 0; pp < 4; ++pp) {
            if (pp < pp0) continue;
            uint32_t bh[4], bl[4];
            const uint32_t b_off = (uint32_t)(((16 * kc + lrow) * BSTRIDE + 16 * pp + lcol8) * 2);
            ldsm_x4_t(sb + b_hi + b_off, bh);
            ldsm_x4_t(sb + b_lo + b_off, bl);
            mma_bf16(C[2 * pp],     Ah[kc], bh);
            mma_bf16(C[2 * pp + 1], Ah[kc], bh + 2);
            mma_bf16(C[2 * pp],     Ah[kc], bl);
            mma_bf16(C[2 * pp + 1], Ah[kc], bl + 2);
            mma_bf16(C[2 * pp],     Al[kc], bh);
            mma_bf16(C[2 * pp + 1], Al[kc], bh + 2);
        }
    }
}

__device__ __forceinline__ void pack_A(const float C[8][4], uint32_t Ah[4][4], uint32_t Al[4][4])
{
    #pragma unroll
    for (int kc = 0; kc < 4; ++kc) {
        split2(C[2 * kc][0],     C[2 * kc][1],     Ah[kc][0], Al[kc][0]);
        split2(C[2 * kc][2],     C[2 * kc][3],     Ah[kc][1], Al[kc][1]);
        split2(C[2 * kc + 1][0], C[2 * kc + 1][1], Ah[kc][2], Al[kc][2]);
        split2(C[2 * kc + 1][2], C[2 * kc + 1][3], Ah[kc][3], Al[kc][3]);
    }
}

// C <- k3*C + k2*T2 + k1*T + k0*I, tiles t >= t0 only (fp16 T2 reads).
__device__ __forceinline__ void combo(const char* smem, float C[8][4],
                                      const float k3, const float k2, const float k1,
                                      const float k0, const int ib, const int jb,
                                      const int t0)
{
    #pragma unroll
    for (int t = 0; t < 8; ++t) {
        if (t < t0) continue;
        const int j0 = 8 * t + jb;
        #pragma unroll
        for (int rr = 0; rr < 2; ++rr) {
            const int i = ib + 8 * rr;
            const uint32_t hw = SMW(SM_T_HI, i, j0);
            const uint32_t lw = SMW(SM_T_LO, i, j0);
            const float2 t2v = __half22float2(
                *reinterpret_cast<const __half2*>(smem + SM_T2 + t2h_off(i, j0)));
            float m0 = k3 * C[t][2 * rr]     + k2 * t2v.x + k1 * (loW(hw) + loW(lw));
            float m1 = k3 * C[t][2 * rr + 1] + k2 * t2v.y + k1 * (hiW(hw) + hiW(lw));
            if (i == j0) m0 += k0;
            if (i == j0 + 1) m1 += k0;
            C[t][2 * rr] = m0;
            C[t][2 * rr + 1] = m1;
        }
    }
}

__global__ void __launch_bounds__(128, 4)
logeig_mma7_kernel(const float* __restrict__ in, float* __restrict__ out, const Coeffs cc)
{
    extern __shared__ __align__(16) char smem[];
    const uint32_t sb = smem_u32(smem);
    const int tid = threadIdx.x;
    const int w = tid >> 5, lane = tid & 31;
    const int grp = lane >> 2, tid4 = lane & 3;
    const int ib = 16 * w + grp;
    const int jb = 2 * tid4;
    const size_t mat = blockIdx.x;

    // ---- build T = s1*A + s0*I as bf16 hi/lo in smem ----
    {
        const float* Ag = in + mat * 4096 + (size_t)(tid >> 1) * 64 + (tid & 1) * 32;
        char* hrow = smem + SM_T_HI + ((tid >> 1) * BSTRIDE + (tid & 1) * 32) * 2;
        char* lrow = smem + SM_T_LO + ((tid >> 1) * BSTRIDE + (tid & 1) * 32) * 2;
        const int di = (tid >> 1) - (tid & 1) * 32;
        #pragma unroll
        for (int q = 0; q < 8; ++q) {
            const float4 v = *reinterpret_cast<const float4*>(Ag + q * 4);
            float t0 = cc.s1 * v.x, t1 = cc.s1 * v.y, t2 = cc.s1 * v.z, t3 = cc.s1 * v.w;
            if (di == q * 4 + 0) t0 += cc.s0;
            if (di == q * 4 + 1) t1 += cc.s0;
            if (di == q * 4 + 2) t2 += cc.s0;
            if (di == q * 4 + 3) t3 += cc.s0;
            uint32_t h0, l0, h1, l1;
            split2(t0, t1, h0, l0);
            split2(t2, t3, h1, l1);
            reinterpret_cast<uint32_t*>(hrow)[2 * q] = h0;
            reinterpret_cast<uint32_t*>(hrow)[2 * q + 1] = h1;
            reinterpret_cast<uint32_t*>(lrow)[2 * q] = l0;
            reinterpret_cast<uint32_t*>(lrow)[2 * q + 1] = l1;
        }
    }
    __syncthreads();

    // ---- A-fragments of T (step0) via ldmatrix non-trans ----
    uint32_t Ah[4][4], Al[4][4];
    {
        const int lrow = lane & 15;
        const int lcol8 = 8 * (lane >> 4);
        #pragma unroll
        for (int kc = 0; kc < 4; ++kc) {
            const uint32_t a_off = (uint32_t)(((16 * w + lrow) * BSTRIDE + 16 * kc + lcol8) * 2);
            ldsm_x4(sb + SM_T_HI + a_off, Ah[kc]);
            ldsm_x4(sb + SM_T_LO + a_off, Al[kc]);
        }
    }

    float C[8][4];

    // ---- step0: C = T*T (T2) -> own-position fp16 STS; A <- split(T2). no sync ----
    mm64_regA(sb, SM_T_HI, SM_T_LO, Ah, Al, lane, C, 0);
    #pragma unroll
    for (int t = 0; t < 8; ++t) {
        const int j0 = 8 * t + jb;
        #pragma unroll
        for (int rr = 0; rr < 2; ++rr) {
            const int i = ib + 8 * rr;
            float2 fv; fv.x = C[t][2 * rr]; fv.y = C[t][2 * rr + 1];
            *reinterpret_cast<__half2*>(smem + SM_T2 + t2h_off(i, j0)) = __float22half2_rn(fv);
        }
    }
    pack_A(C, Ah, Al);

    // ---- step1: C = T2*T (T3) -> STS bf16 T3; combo M = a9 C + a8 T2 + a7 T + a6 I ----
    mm64_regA(sb, SM_T_HI, SM_T_LO, Ah, Al, lane, C, 0);
    #pragma unroll
    for (int t = 0; t < 8; ++t) {
        const int j0 = 8 * t + jb;
        #pragma unroll
        for (int rr = 0; rr < 2; ++rr) {
            const int i = ib + 8 * rr;
            uint32_t hw, lw;
            split2(C[t][2 * rr], C[t][2 * rr + 1], hw, lw);
            *reinterpret_cast<uint32_t*>(smem + SM_T3_HI + (i * BSTRIDE + j0) * 2) = hw;
            *reinterpret_cast<uint32_t*>(smem + SM_T3_LO + (i * BSTRIDE + j0) * 2) = lw;
        }
    }
    combo(smem, C, cc.a[9], cc.a[8], cc.a[7], cc.a[6], ib, jb, 0);
    pack_A(C, Ah, Al);
    __syncthreads();   // T3 visible to all warps

    // ---- step2: C = M*T3 ; combo M' = C + a5 T2 + a4 T + a3 I ----
    mm64_regA(sb, SM_T3_HI, SM_T3_LO, Ah, Al, lane, C, 0);
    combo(smem, C, 1.0f, cc.a[5], cc.a[4], cc.a[3], ib, jb, 0);
    pack_A(C, Ah, Al);
    // no sync: B (T3) unchanged

    // ---- step3: only column tiles >= warp's diagonal block ----
    mm64_regA(sb, SM_T3_HI, SM_T3_LO, Ah, Al, lane, C, w);
    combo(smem, C, 1.0f, cc.a[2], cc.a[1], cc.a[0], ib, jb, 2 * w);

    // ---- epilogue direct from regs ----
    {
        const float SQ2 = 1.41421356237309515f;
        float* ob = out + mat * 2080;
        #pragma unroll
        for (int rr = 0; rr < 2; ++rr) {
            const int i = ib + 8 * rr;
            const int rowbase = i * (129 - i) / 2 - i;
            #pragma unroll
            for (int t = 0; t < 8; ++t) {
                if (t < 2 * w) continue;
                const int j0 = 8 * t + jb;
                #pragma unroll
                for (int c = 0; c < 2; ++c) {
                    const int j = j0 + c;
                    if (j >= i) {
                        const float v = fabsf(C[t][2 * rr + c]);
                        ob[rowbase + j] = (i == j) ? v : v * SQ2;
                    }
                }
            }
        }
    }
}

extern "C" void kernel_launch(void* const* d_in, const int* in_sizes, int n_in,
                              void* d_out, int out_size)
{
    const float* in = (const float*)d_in[0];
    float* out = (float*)d_out;
    const int nmat = in_sizes[0] / 4096;

    // Chebyshev series of log on [a,b] -> monomial coeffs in t (well-conditioned).
    const double a = 0.97, b = 7.0;
    const double mm = 0.5 * (a + b);
    const double wdl = (b - a) / (b + a);
    const double z = (sqrt(1.0 - wdl * wdl) - 1.0) / wdl;

    double c[NDEG + 1];
    c[0] = log(mm) - log(1.0 + z * z);
    double zk = 1.0;
    for (int k = 1; k <= NDEG; ++k) { zk *= z; c[k] = -2.0 * zk / (double)k; }

    double am[NDEG + 1];
    for (int j = 0; j <= NDEG; ++j) am[j] = 0.0;
    {
        double Tm1[NDEG + 1] = {0}, Tk[NDEG + 1] = {0}, Tn[NDEG + 1];
        Tm1[0] = 1.0;
        Tk[1] = 1.0;
        am[0] += c[0] * Tm1[0];
        am[1] += c[1] * Tk[1];
        for (int k = 2; k <= NDEG; ++k) {
            for (int j = 0; j <= NDEG; ++j) Tn[j] = -Tm1[j];
            for (int j = 1; j <= NDEG; ++j) Tn[j] += 2.0 * Tk[j - 1];
            for (int j = 0; j <= NDEG; ++j) { am[j] += c[k] * Tn[j]; Tm1[j] = Tk[j]; Tk[j] = Tn[j]; }
        }
    }

    Coeffs cc;
    for (int j = 0; j <= NDEG; ++j) cc.a[j] = (float)am[j];
    cc.s1 = (float)(2.0 / (b - a));
    cc.s0 = (float)(-(a + b) / (b - a));

    cudaFuncSetAttribute(logeig_mma7_kernel,
                         cudaFuncAttributeMaxDynamicSharedMemorySize, SMEM_BYTES);
    logeig_mma7_kernel<<<nmat, 128, SMEM_BYTES>>>(in, out, cc);
}

// round 11
// speedup vs baseline: 1.4785x; 1.1537x over previous
#include <cuda_runtime.h>
#include <cuda_bf16.h>
#include <math.h>
#include <stdint.h>

struct Coeffs {
    float s1, s0;            // T = s1*A + s0*I
    float p;                 // V = (y0 + p*T)*y0
    float q1, r1, sf1;       // F1 = V + q1*y0 + r1*T + sf1*I
    float q2, r2, sf2;       // F2 = V + q2*y0 + r2*T + sf2*I
    float a8;                // p(T) = a8*(F1*F2) + kc12*y0 + kc13*T + kc14*I
    float kc12, kc13, kc14;
};

// smem: bf16 hi/lo matrices: T, y0=T^2, F2.
#define BSTRIDE 72
#define BMATB   (64 * BSTRIDE * 2)        // 9216
#define SM_T_HI  0
#define SM_T_LO  (1 * BMATB)
#define SM_Y_HI  (2 * BMATB)
#define SM_Y_LO  (3 * BMATB)
#define SM_F_HI  (4 * BMATB)
#define SM_F_LO  (5 * BMATB)
#define SMEM_BYTES (6 * BMATB)            // 55296

__device__ __forceinline__ uint32_t smem_u32(const void* p) {
    uint32_t r;
    asm("{ .reg .u64 t; cvta.to.shared.u64 t, %1; cvt.u32.u64 %0, t; }" : "=r"(r) : "l"(p));
    return r;
}
__device__ __forceinline__ void ldsm_x4(uint32_t addr, uint32_t* r) {
    asm volatile("ldmatrix.sync.aligned.m8n8.x4.shared.b16 {%0,%1,%2,%3}, [%4];"
        : "=r"(r[0]), "=r"(r[1]), "=r"(r[2]), "=r"(r[3]) : "r"(addr));
}
__device__ __forceinline__ void ldsm_x4_t(uint32_t addr, uint32_t* r) {
    asm volatile("ldmatrix.sync.aligned.m8n8.x4.trans.shared.b16 {%0,%1,%2,%3}, [%4];"
        : "=r"(r[0]), "=r"(r[1]), "=r"(r[2]), "=r"(r[3]) : "r"(addr));
}
__device__ __forceinline__ void mma_bf16(float* c, const uint32_t* a, const uint32_t* b) {
    asm volatile("mma.sync.aligned.m16n8k16.row.col.f32.bf16.bf16.f32 "
        "{%0,%1,%2,%3}, {%4,%5,%6,%7}, {%8,%9}, {%0,%1,%2,%3};"
        : "+f"(c[0]), "+f"(c[1]), "+f"(c[2]), "+f"(c[3])
        : "r"(a[0]), "r"(a[1]), "r"(a[2]), "r"(a[3]), "r"(b[0]), "r"(b[1]));
}
__device__ __forceinline__ float loW(uint32_t w) { return __uint_as_float(w << 16); }
__device__ __forceinline__ float hiW(uint32_t w) { return __uint_as_float(w & 0xFFFF0000u); }

// fast split: packed cvt for hi pair, exact residual, packed cvt for lo pair
__device__ __forceinline__ void split2(float x0, float x1, uint32_t& hw, uint32_t& lw) {
    asm("cvt.rn.bf16x2.f32 %0, %1, %2;" : "=r"(hw) : "f"(x1), "f"(x0));
    const float l0 = x0 - loW(hw);
    const float l1 = x1 - hiW(hw);
    asm("cvt.rn.bf16x2.f32 %0, %1, %2;" : "=r"(lw) : "f"(l1), "f"(l0));
}

#define SMW(buf, i, j) (*reinterpret_cast<const uint32_t*>(smem + (buf) + ((i) * BSTRIDE + (j)) * 2))

// C = (Ah+Al)(Bh+Bl): A frags in regs, B via ldmatrix.trans; skip column blocks pp < pp0.
__device__ __forceinline__ void mm64_regA(const uint32_t sb, const int b_hi, const int b_lo,
                                          const uint32_t Ah[4][4], const uint32_t Al[4][4],
                                          const int lane, float C[8][4], const int pp0)
{
    #pragma unroll
    for (int t = 0; t < 8; ++t)
        #pragma unroll
        for (int r = 0; r < 4; ++r) C[t][r] = 0.0f;

    const int lrow = lane & 15;
    const int lcol8 = 8 * (lane >> 4);

    #pragma unroll
    for (int kc = 0; kc < 4; ++kc) {
        #pragma unroll
        for (int pp = 0; pp < 4; ++pp) {
            if (pp < pp0) continue;
            uint32_t bh[4], bl[4];
            const uint32_t b_off = (uint32_t)(((16 * kc + lrow) * BSTRIDE + 16 * pp + lcol8) * 2);
            ldsm_x4_t(sb + b_hi + b_off, bh);
            ldsm_x4_t(sb + b_lo + b_off, bl);
            mma_bf16(C[2 * pp],     Ah[kc], bh);
            mma_bf16(C[2 * pp + 1], Ah[kc], bh + 2);
            mma_bf16(C[2 * pp],     Ah[kc], bl);
            mma_bf16(C[2 * pp + 1], Ah[kc], bl + 2);
            mma_bf16(C[2 * pp],     Al[kc], bh);
            mma_bf16(C[2 * pp + 1], Al[kc], bh + 2);
        }
    }
}

__global__ void __launch_bounds__(128, 4)
logeig_s8_kernel(const float* __restrict__ in, float* __restrict__ out, const Coeffs cc)
{
    extern __shared__ __align__(16) char smem[];
    const uint32_t sb = smem_u32(smem);
    const int tid = threadIdx.x;
    const int w = tid >> 5, lane = tid & 31;
    const int grp = lane >> 2, tid4 = lane & 3;
    const int ib = 16 * w + grp;
    const int jb = 2 * tid4;
    const size_t mat = blockIdx.x;

    // ---- build T = s1*A + s0*I as bf16 hi/lo in smem ----
    {
        const float* Ag = in + mat * 4096 + (size_t)(tid >> 1) * 64 + (tid & 1) * 32;
        char* hrow = smem + SM_T_HI + ((tid >> 1) * BSTRIDE + (tid & 1) * 32) * 2;
        char* lrow = smem + SM_T_LO + ((tid >> 1) * BSTRIDE + (tid & 1) * 32) * 2;
        const int di = (tid >> 1) - (tid & 1) * 32;
        #pragma unroll
        for (int q = 0; q < 8; ++q) {
            const float4 v = *reinterpret_cast<const float4*>(Ag + q * 4);
            float t0 = cc.s1 * v.x, t1 = cc.s1 * v.y, t2 = cc.s1 * v.z, t3 = cc.s1 * v.w;
            if (di == q * 4 + 0) t0 += cc.s0;
            if (di == q * 4 + 1) t1 += cc.s0;
            if (di == q * 4 + 2) t2 += cc.s0;
            if (di == q * 4 + 3) t3 += cc.s0;
            uint32_t h0, l0, h1, l1;
            split2(t0, t1, h0, l0);
            split2(t2, t3, h1, l1);
            reinterpret_cast<uint32_t*>(hrow)[2 * q] = h0;
            reinterpret_cast<uint32_t*>(hrow)[2 * q + 1] = h1;
            reinterpret_cast<uint32_t*>(lrow)[2 * q] = l0;
            reinterpret_cast<uint32_t*>(lrow)[2 * q + 1] = l1;
        }
    }
    __syncthreads();

    // ---- A-fragments of T via ldmatrix non-trans ----
    uint32_t Ah[4][4], Al[4][4];
    {
        const int lrow = lane & 15;
        const int lcol8 = 8 * (lane >> 4);
        #pragma unroll
        for (int kc = 0; kc < 4; ++kc) {
            const uint32_t a_off = (uint32_t)(((16 * w + lrow) * BSTRIDE + 16 * kc + lcol8) * 2);
            ldsm_x4(sb + SM_T_HI + a_off, Ah[kc]);
            ldsm_x4(sb + SM_T_LO + a_off, Al[kc]);
        }
    }

    float C[8][4];

    // ---- M1: C = T*T = y0 ; STS y0 hi/lo ; A <- split(y0 + p*T) (T still in Ah/Al) ----
    mm64_regA(sb, SM_T_HI, SM_T_LO, Ah, Al, lane, C, 0);
    #pragma unroll
    for (int t = 0; t < 8; ++t) {
        const int j0 = 8 * t + jb;
        #pragma unroll
        for (int rr = 0; rr < 2; ++rr) {
            const int i = ib + 8 * rr;
            uint32_t hw, lw;
            split2(C[t][2 * rr], C[t][2 * rr + 1], hw, lw);
            *reinterpret_cast<uint32_t*>(smem + SM_Y_HI + (i * BSTRIDE + j0) * 2) = hw;
            *reinterpret_cast<uint32_t*>(smem + SM_Y_LO + (i * BSTRIDE + j0) * 2) = lw;
        }
    }
    #pragma unroll
    for (int kc = 0; kc < 4; ++kc) {
        #pragma unroll
        for (int q = 0; q < 4; ++q) {
            const uint32_t th = Ah[kc][q], tl = Al[kc][q];
            const int t = 2 * kc + (q >> 1), rr = q & 1;
            const float x0 = C[t][2 * rr]     + cc.p * (loW(th) + loW(tl));
            const float x1 = C[t][2 * rr + 1] + cc.p * (hiW(th) + hiW(tl));
            split2(x0, x1, Ah[kc][q], Al[kc][q]);
        }
    }
    __syncthreads();   // y0 visible

    // ---- M2: C = (y0 + p*T)*y0 = V ; build F1 -> A, F2 -> STS ----
    mm64_regA(sb, SM_Y_HI, SM_Y_LO, Ah, Al, lane, C, 0);
    #pragma unroll
    for (int t = 0; t < 8; ++t) {
        const int j0 = 8 * t + jb;
        #pragma unroll
        for (int rr = 0; rr < 2; ++rr) {
            const int i = ib + 8 * rr;
            const uint32_t th = SMW(SM_T_HI, i, j0), tl = SMW(SM_T_LO, i, j0);
            const uint32_t yh = SMW(SM_Y_HI, i, j0), yl = SMW(SM_Y_LO, i, j0);
            const float T0 = loW(th) + loW(tl), T1 = hiW(th) + hiW(tl);
            const float Y0 = loW(yh) + loW(yl), Y1 = hiW(yh) + hiW(yl);
            float f10 = C[t][2 * rr]     + cc.q1 * Y0 + cc.r1 * T0;
            float f11 = C[t][2 * rr + 1] + cc.q1 * Y1 + cc.r1 * T1;
            float f20 = C[t][2 * rr]     + cc.q2 * Y0 + cc.r2 * T0;
            float f21 = C[t][2 * rr + 1] + cc.q2 * Y1 + cc.r2 * T1;
            if (i == j0)     { f10 += cc.sf1; f20 += cc.sf2; }
            if (i == j0 + 1) { f11 += cc.sf1; f21 += cc.sf2; }
            split2(f10, f11, Ah[t >> 1][(t & 1) * 2 + rr], Al[t >> 1][(t & 1) * 2 + rr]);
            uint32_t hw, lw;
            split2(f20, f21, hw, lw);
            *reinterpret_cast<uint32_t*>(smem + SM_F_HI + (i * BSTRIDE + j0) * 2) = hw;
            *reinterpret_cast<uint32_t*>(smem + SM_F_LO + (i * BSTRIDE + j0) * 2) = lw;
        }
    }
    __syncthreads();   // F2 visible

    // ---- M3: C = F1*F2 (triangle-restricted) ----
    mm64_regA(sb, SM_F_HI, SM_F_LO, Ah, Al, lane, C, w);

    // ---- final combo + epilogue: p(T) = a8*C + kc12*y0 + kc13*T + kc14*I ----
    {
        const float SQ2 = 1.41421356237309515f;
        float* ob = out + mat * 2080;
        #pragma unroll
        for (int t = 0; t < 8; ++t) {
            if (t < 2 * w) continue;
            const int j0 = 8 * t + jb;
            #pragma unroll
            for (int rr = 0; rr < 2; ++rr) {
                const int i = ib + 8 * rr;
                const uint32_t th = SMW(SM_T_HI, i, j0), tl = SMW(SM_T_LO, i, j0);
                const uint32_t yh = SMW(SM_Y_HI, i, j0), yl = SMW(SM_Y_LO, i, j0);
                float f0 = cc.a8 * C[t][2 * rr]     + cc.kc12 * (loW(yh) + loW(yl))
                         + cc.kc13 * (loW(th) + loW(tl));
                float f1 = cc.a8 * C[t][2 * rr + 1] + cc.kc12 * (hiW(yh) + hiW(yl))
                         + cc.kc13 * (hiW(th) + hiW(tl));
                if (i == j0)     f0 += cc.kc14;
                if (i == j0 + 1) f1 += cc.kc14;
                const int rowbase = i * (129 - i) / 2 - i;
                if (j0 >= i)     ob[rowbase + j0]     = (i == j0)     ? fabsf(f0) : fabsf(f0) * SQ2;
                if (j0 + 1 >= i) ob[rowbase + j0 + 1] = (i == j0 + 1) ? fabsf(f1) : fabsf(f1) * SQ2;
            }
        }
    }
}

extern "C" void kernel_launch(void* const* d_in, const int* in_sizes, int n_in,
                              void* d_out, int out_size)
{
    const float* in = (const float*)d_in[0];
    float* out = (float*)d_out;
    const int nmat = in_sizes[0] / 4096;

    // Chebyshev series of log on [a,b], truncated at degree 8 -> monomials in t.
    const double a = 0.97, b = 7.0;
    const double mm = 0.5 * (a + b);
    const double wdl = (b - a) / (b + a);
    const double z = (sqrt(1.0 - wdl * wdl) - 1.0) / wdl;

    const int ND = 8;
    double c[ND + 1];
    c[0] = log(mm) - log(1.0 + z * z);
    double zk = 1.0;
    for (int k = 1; k <= ND; ++k) { zk *= z; c[k] = -2.0 * zk / (double)k; }

    double am[ND + 1];
    for (int j = 0; j <= ND; ++j) am[j] = 0.0;
    {
        double Tm1[ND + 1] = {0}, Tk[ND + 1] = {0}, Tn[ND + 1];
        Tm1[0] = 1.0;
        Tk[1] = 1.0;
        am[0] += c[0] * Tm1[0];
        am[1] += c[1] * Tk[1];
        for (int k = 2; k <= ND; ++k) {
            for (int j = 0; j <= ND; ++j) Tn[j] = -Tm1[j];
            for (int j = 1; j <= ND; ++j) Tn[j] += 2.0 * Tk[j - 1];
            for (int j = 0; j <= ND; ++j) { am[j] += c[k] * Tn[j]; Tm1[j] = Tk[j]; Tk[j] = Tn[j]; }
        }
    }

    // 3-product scheme coefficients (closed form).
    const double a8 = am[8];
    double bb[8];
    for (int k = 0; k < 8; ++k) bb[k] = am[k] / a8;

    const double p  = bb[7] / 2.0;
    const double Q  = bb[6] - p * p;
    const double R  = bb[5] - p * Q;
    const double dq = 1.0;
    const double S  = bb[4] - p * R - Q * Q / 4.0 + dq * dq;
    const double dr = (p * S + Q * R / 2.0 - bb[3]) / (2.0 * dq);
    const double q1 = Q / 2.0 + dq, q2 = Q / 2.0 - dq;
    const double r1 = R / 2.0 + dr, r2 = R / 2.0 - dr;
    const double s1 = S / 2.0,      s2 = S / 2.0;
    const double c12 = bb[2] - Q * S / 2.0 - R * R / 4.0 + dr * dr;
    const double c13 = bb[1] - R * S / 2.0;
    const double c14 = bb[0] - S * S / 4.0;

    Coeffs cc;
    cc.s1 = (float)(2.0 / (b - a));
    cc.s0 = (float)(-(a + b) / (b - a));
    cc.p  = (float)p;
    cc.q1 = (float)q1; cc.r1 = (float)r1; cc.sf1 = (float)s1;
    cc.q2 = (float)q2; cc.r2 = (float)r2; cc.sf2 = (float)s2;
    cc.a8 = (float)a8;
    cc.kc12 = (float)(a8 * c12);
    cc.kc13 = (float)(a8 * c13);
    cc.kc14 = (float)(a8 * c14);

    cudaFuncSetAttribute(logeig_s8_kernel,
                         cudaFuncAttributeMaxDynamicSharedMemorySize, SMEM_BYTES);
    logeig_s8_kernel<<<nmat, 128, SMEM_BYTES>>>(in, out, cc);
}